// round 6
// baseline (speedup 1.0000x reference)
#include <cuda_runtime.h>
#include <cuda_bf16.h>

#define GG   256      // graphs
#define DD   128      // feature dim
#define ROWS_PER_WARP 256
#define ACC_THREADS   256   // 8 warps per CTA

// Zero-initialized at module load; finalize_kernel re-zeros after consuming,
// so the invariant "scratch is zero at accum launch" holds on every graph replay.
__device__ float g_sums[GG * DD];
__device__ float g_counts[GG];

__device__ __forceinline__ int load_g(const void* batch, long long i, int is64) {
    if (is64) return (int)((const long long*)batch)[i];
    return ((const int*)batch)[i];
}

__device__ __forceinline__ void flush_seg(int g, float4 acc, int cnt, int lane) {
    if (cnt == 0) return;
    float* s = g_sums + (long long)g * DD + lane * 4;
    atomicAdd(s + 0, acc.x);
    atomicAdd(s + 1, acc.y);
    atomicAdd(s + 2, acc.z);
    atomicAdd(s + 3, acc.w);
    if (lane == 0) atomicAdd(&g_counts[g], (float)cnt);
}

// Streaming segment-sum. One warp owns ROWS_PER_WARP contiguous rows; lane l
// accumulates columns [4l, 4l+4) in a float4. ~97% of warps take the
// single-segment fast path (batch sorted, avg segment ~7813 rows).
__global__ void accum_kernel(const float4* __restrict__ x4,
                             const void* __restrict__ batch, int N) {
    // dtype probe: int32 word N-1 is the high half of int64 element 999,999 (=0)
    // if batch is int64, but the sorted max (>0) if int32.
    const int is64 = (((const int*)batch)[N - 1] == 0);
    const int lane = threadIdx.x & 31;
    const long long warp = (long long)(blockIdx.x * (ACC_THREADS / 32)) + (threadIdx.x >> 5);
    long long r0 = warp * ROWS_PER_WARP;
    if (r0 >= N) return;
    long long r1 = r0 + ROWS_PER_WARP;
    if (r1 > N) r1 = N;

    const int gfirst = load_g(batch, r0, is64);
    const int glast  = load_g(batch, r1 - 1, is64);

    if (gfirst == glast) {
        // ---- fast path: whole block in one segment ----
        float4 acc = make_float4(0.f, 0.f, 0.f, 0.f);
        long long r = r0;
        for (; r + 8 <= r1; r += 8) {
            float4 v[8];
            #pragma unroll
            for (int k = 0; k < 8; k++)
                v[k] = __ldcs(&x4[(r + k) * 32 + lane]);   // evict-first stream
            #pragma unroll
            for (int k = 0; k < 8; k++) {
                acc.x += v[k].x; acc.y += v[k].y;
                acc.z += v[k].z; acc.w += v[k].w;
            }
        }
        for (; r < r1; r++) {   // only the final partial warp hits this
            float4 v = __ldcs(&x4[r * 32 + lane]);
            acc.x += v.x; acc.y += v.y; acc.z += v.z; acc.w += v.w;
        }
        flush_seg(gfirst, acc, (int)(r1 - r0), lane);
        return;
    }

    // ---- slow path: segment boundary inside this block (~3% of warps) ----
    float4 acc = make_float4(0.f, 0.f, 0.f, 0.f);
    int cnt = 0;
    int cur = gfirst;

    long long r = r0;
    for (; r + 4 <= r1; r += 4) {
        int ga = load_g(batch, r,     is64);
        int gd = load_g(batch, r + 3, is64);
        float4 v0 = __ldcs(&x4[(r    ) * 32 + lane]);
        float4 v1 = __ldcs(&x4[(r + 1) * 32 + lane]);
        float4 v2 = __ldcs(&x4[(r + 2) * 32 + lane]);
        float4 v3 = __ldcs(&x4[(r + 3) * 32 + lane]);
        if (ga == cur && gd == cur) {
            acc.x += (v0.x + v1.x) + (v2.x + v3.x);
            acc.y += (v0.y + v1.y) + (v2.y + v3.y);
            acc.z += (v0.z + v1.z) + (v2.z + v3.z);
            acc.w += (v0.w + v1.w) + (v2.w + v3.w);
            cnt += 4;
        } else {
            int gs[4];
            gs[0] = ga;
            gs[1] = load_g(batch, r + 1, is64);
            gs[2] = load_g(batch, r + 2, is64);
            gs[3] = gd;
            float4 vs[4] = {v0, v1, v2, v3};
            #pragma unroll
            for (int k = 0; k < 4; k++) {
                if (gs[k] != cur) {
                    flush_seg(cur, acc, cnt, lane);
                    acc = make_float4(0.f, 0.f, 0.f, 0.f);
                    cnt = 0;
                    cur = gs[k];
                }
                acc.x += vs[k].x; acc.y += vs[k].y;
                acc.z += vs[k].z; acc.w += vs[k].w;
                cnt++;
            }
        }
    }
    for (; r < r1; r++) {
        int g = load_g(batch, r, is64);
        float4 v = __ldcs(&x4[r * 32 + lane]);
        if (g != cur) {
            flush_seg(cur, acc, cnt, lane);
            acc = make_float4(0.f, 0.f, 0.f, 0.f);
            cnt = 0;
            cur = g;
        }
        acc.x += v.x; acc.y += v.y; acc.z += v.z; acc.w += v.w;
        cnt++;
    }
    flush_seg(cur, acc, cnt, lane);
}

// Mean + MLP head. One block per graph, 256 threads.
// Thread t: hidden unit j = t&63, quarter q = t>>6 covering d in [32q, 32q+32).
// 4-way d-split cuts the dependent FMA/load chain 128->32 and gives 4x the
// warps to hide L2 latency on the W1 loads (coalesced across j).
// Consumes g_sums/g_counts then re-zeros them for the next graph replay.
__global__ void finalize_kernel(const float* __restrict__ W1,
                                const float* __restrict__ b1,
                                const float* __restrict__ W2,
                                const float* __restrict__ b2,
                                float* __restrict__ out) {
    const int g = blockIdx.x;
    const int t = threadIdx.x;     // 0..255
    const int j = t & 63;          // hidden unit
    const int q = t >> 6;          // d-quarter
    __shared__ float mean_s[DD];
    __shared__ float hh[256];

    float inv = 1.0f / g_counts[g];          // all threads read before re-zero
    if (t < DD) mean_s[t] = g_sums[g * DD + t] * inv;
    __syncthreads();                         // orders reads before re-zero

    // restore zero-invariant for the next replay
    if (t < DD) g_sums[g * DD + t] = 0.0f;
    if (t == 0) g_counts[g] = 0.0f;

    float h = 0.0f;
    const int dbase = q * 32;
    #pragma unroll
    for (int d0 = 0; d0 < 32; d0++) {
        int d = dbase + d0;
        h = fmaf(mean_s[d], W1[d * 64 + j], h);   // W1 is [128,64] row-major
    }
    hh[t] = h;
    __syncthreads();

    if (t < 64) {
        float hv = (hh[t] + hh[t + 64]) + (hh[t + 128] + hh[t + 192]) + b1[t];
        hv = fmaxf(hv, 0.0f);
        hh[t] = hv * W2[t];
    }
    __syncthreads();

    if (t < 32) {
        float v = hh[t] + hh[t + 32];
        #pragma unroll
        for (int s = 16; s > 0; s >>= 1)
            v += __shfl_down_sync(0xffffffffu, v, s);
        if (t == 0) out[g] = v + b2[0];
    }
}

extern "C" void kernel_launch(void* const* d_in, const int* in_sizes, int n_in,
                              void* d_out, int out_size) {
    const float* x     = (const float*)d_in[0];
    const void*  batch = d_in[1];
    const float* W1    = (const float*)d_in[2];
    const float* b1    = (const float*)d_in[3];
    const float* W2    = (const float*)d_in[4];
    const float* b2    = (const float*)d_in[5];
    float* out = (float*)d_out;

    const int N = in_sizes[0] / DD;   // 2,000,000

    int warps = (N + ROWS_PER_WARP - 1) / ROWS_PER_WARP;
    int ctas  = (warps + (ACC_THREADS / 32) - 1) / (ACC_THREADS / 32);
    accum_kernel<<<ctas, ACC_THREADS>>>((const float4*)x, batch, N);

    finalize_kernel<<<GG, 256>>>(W1, b1, W2, b2, out);
}

// round 9
// speedup vs baseline: 1.0234x; 1.0234x over previous
#include <cuda_runtime.h>
#include <cuda_bf16.h>

#define GG   256      // graphs
#define DD   128      // feature dim
#define ROWS_PER_WARP 128
#define ACC_THREADS   256   // 8 warps per CTA

// Zero-initialized at module load; finalize_kernel re-zeros after consuming,
// so the invariant "scratch is zero at accum launch" holds on every graph replay.
__device__ float g_sums[GG * DD];
__device__ float g_counts[GG];

__device__ __forceinline__ int load_g(const void* batch, long long i, int is64) {
    if (is64) return (int)((const long long*)batch)[i];
    return ((const int*)batch)[i];
}

__device__ __forceinline__ void flush_seg(int g, float4 acc, int cnt, int lane) {
    if (cnt == 0) return;
    float* s = g_sums + (long long)g * DD + lane * 4;
    atomicAdd(s + 0, acc.x);
    atomicAdd(s + 1, acc.y);
    atomicAdd(s + 2, acc.z);
    atomicAdd(s + 3, acc.w);
    if (lane == 0) atomicAdd(&g_counts[g], (float)cnt);
}

// Streaming segment-sum. One warp owns ROWS_PER_WARP contiguous rows; lane l
// accumulates columns [4l, 4l+4) in a float4. Batch is sorted, avg segment
// ~7813 rows >> 128, so ~98% of warps take the single-segment fast path.
__global__ void accum_kernel(const float4* __restrict__ x4,
                             const void* __restrict__ batch, int N) {
    // dtype probe: int32 word N-1 is the high half of int64 element 999,999 (=0)
    // if batch is int64, but the sorted max (>0) if int32.
    const int is64 = (((const int*)batch)[N - 1] == 0);
    const int lane = threadIdx.x & 31;
    const long long warp = (long long)(blockIdx.x * (ACC_THREADS / 32)) + (threadIdx.x >> 5);
    long long r0 = warp * ROWS_PER_WARP;
    if (r0 >= N) return;
    long long r1 = r0 + ROWS_PER_WARP;
    if (r1 > N) r1 = N;

    const int gfirst = load_g(batch, r0, is64);
    const int glast  = load_g(batch, r1 - 1, is64);

    if (gfirst == glast) {
        // ---- fast path: whole block in one segment ----
        float4 acc = make_float4(0.f, 0.f, 0.f, 0.f);
        long long r = r0;
        for (; r + 8 <= r1; r += 8) {
            float4 v[8];
            #pragma unroll
            for (int k = 0; k < 8; k++)
                v[k] = __ldcs(&x4[(r + k) * 32 + lane]);   // evict-first stream
            #pragma unroll
            for (int k = 0; k < 8; k++) {
                acc.x += v[k].x; acc.y += v[k].y;
                acc.z += v[k].z; acc.w += v[k].w;
            }
        }
        for (; r < r1; r++) {   // only the final partial warp hits this
            float4 v = __ldcs(&x4[r * 32 + lane]);
            acc.x += v.x; acc.y += v.y; acc.z += v.z; acc.w += v.w;
        }
        flush_seg(gfirst, acc, (int)(r1 - r0), lane);
        return;
    }

    // ---- slow path: segment boundary inside this block (~2% of warps) ----
    float4 acc = make_float4(0.f, 0.f, 0.f, 0.f);
    int cnt = 0;
    int cur = gfirst;

    long long r = r0;
    for (; r + 4 <= r1; r += 4) {
        int ga = load_g(batch, r,     is64);
        int gd = load_g(batch, r + 3, is64);
        float4 v0 = __ldcs(&x4[(r    ) * 32 + lane]);
        float4 v1 = __ldcs(&x4[(r + 1) * 32 + lane]);
        float4 v2 = __ldcs(&x4[(r + 2) * 32 + lane]);
        float4 v3 = __ldcs(&x4[(r + 3) * 32 + lane]);
        if (ga == cur && gd == cur) {
            acc.x += (v0.x + v1.x) + (v2.x + v3.x);
            acc.y += (v0.y + v1.y) + (v2.y + v3.y);
            acc.z += (v0.z + v1.z) + (v2.z + v3.z);
            acc.w += (v0.w + v1.w) + (v2.w + v3.w);
            cnt += 4;
        } else {
            int gs[4];
            gs[0] = ga;
            gs[1] = load_g(batch, r + 1, is64);
            gs[2] = load_g(batch, r + 2, is64);
            gs[3] = gd;
            float4 vs[4] = {v0, v1, v2, v3};
            #pragma unroll
            for (int k = 0; k < 4; k++) {
                if (gs[k] != cur) {
                    flush_seg(cur, acc, cnt, lane);
                    acc = make_float4(0.f, 0.f, 0.f, 0.f);
                    cnt = 0;
                    cur = gs[k];
                }
                acc.x += vs[k].x; acc.y += vs[k].y;
                acc.z += vs[k].z; acc.w += vs[k].w;
                cnt++;
            }
        }
    }
    for (; r < r1; r++) {
        int g = load_g(batch, r, is64);
        float4 v = __ldcs(&x4[r * 32 + lane]);
        if (g != cur) {
            flush_seg(cur, acc, cnt, lane);
            acc = make_float4(0.f, 0.f, 0.f, 0.f);
            cnt = 0;
            cur = g;
        }
        acc.x += v.x; acc.y += v.y; acc.z += v.z; acc.w += v.w;
        cnt++;
    }
    flush_seg(cur, acc, cnt, lane);
}

// Mean + MLP head. One block per graph, 256 threads.
// Latency-chain fix: W1 (32KB) is prefetched into smem with independent
// LDG.128s concurrently with the raw-sum loads; h is computed from RAW sums
// and 1/count is folded in afterwards (layer is linear), so g_counts never
// sits on the critical path. FMA loop runs off conflict-free LDS.
// Thread t: hidden unit j = t&63, quarter q = t>>6 covering d in [32q,32q+32).
__global__ void finalize_kernel(const float* __restrict__ W1,
                                const float* __restrict__ b1,
                                const float* __restrict__ W2,
                                const float* __restrict__ b2,
                                float* __restrict__ out) {
    const int g = blockIdx.x;
    const int t = threadIdx.x;     // 0..255
    const int j = t & 63;          // hidden unit
    const int q = t >> 6;          // d-quarter
    __shared__ float w1s[DD * 64];     // 32 KB
    __shared__ float sum_s[DD];
    __shared__ float hh[256];

    // Independent prefetches — all pipelined, nothing serial.
    const float4* W14 = (const float4*)W1;     // 2048 float4
    float4 wv[8];
    #pragma unroll
    for (int i = 0; i < 8; i++) wv[i] = W14[t + i * 256];
    float cntv = g_counts[g];                  // off critical path now
    if (t < DD) sum_s[t] = g_sums[g * DD + t]; // raw sums (no /count yet)
    #pragma unroll
    for (int i = 0; i < 8; i++) ((float4*)w1s)[t + i * 256] = wv[i];
    __syncthreads();

    // restore zero-invariant for the next replay (all reads done above)
    if (t < DD) g_sums[g * DD + t] = 0.0f;
    if (t == 0) g_counts[g] = 0.0f;

    float h = 0.0f;
    const int dbase = q * 32;
    #pragma unroll
    for (int d0 = 0; d0 < 32; d0++) {
        int d = dbase + d0;
        h = fmaf(sum_s[d], w1s[d * 64 + j], h);   // consecutive j -> no bank conflict
    }
    hh[t] = h;
    __syncthreads();

    if (t < 64) {
        float inv = 1.0f / cntv;
        float hv = ((hh[t] + hh[t + 64]) + (hh[t + 128] + hh[t + 192])) * inv + b1[t];
        hv = fmaxf(hv, 0.0f);
        hh[t] = hv * W2[t];
    }
    __syncthreads();

    if (t < 32) {
        float v = hh[t] + hh[t + 32];
        #pragma unroll
        for (int s = 16; s > 0; s >>= 1)
            v += __shfl_down_sync(0xffffffffu, v, s);
        if (t == 0) out[g] = v + b2[0];
    }
}

extern "C" void kernel_launch(void* const* d_in, const int* in_sizes, int n_in,
                              void* d_out, int out_size) {
    const float* x     = (const float*)d_in[0];
    const void*  batch = d_in[1];
    const float* W1    = (const float*)d_in[2];
    const float* b1    = (const float*)d_in[3];
    const float* W2    = (const float*)d_in[4];
    const float* b2    = (const float*)d_in[5];
    float* out = (float*)d_out;

    const int N = in_sizes[0] / DD;   // 2,000,000

    int warps = (N + ROWS_PER_WARP - 1) / ROWS_PER_WARP;
    int ctas  = (warps + (ACC_THREADS / 32) - 1) / (ACC_THREADS / 32);
    accum_kernel<<<ctas, ACC_THREADS>>>((const float4*)x, batch, N);

    finalize_kernel<<<GG, 256>>>(W1, b1, W2, b2, out);
}